// round 6
// baseline (speedup 1.0000x reference)
#include <cuda_runtime.h>
#include <cuda_fp16.h>
#include <cstdint>

// Conv 7x7 C=1 as implicit GEMM via mma.sync (legacy HMMA path; tcgen05 is
// rejected by this harness's family-level compute_103 ptxas target).
// D[pixel(112), filter(64)] = A[pix, K=64] . B[filt, K=64]^T, K = ky*8+kx.
// fp16 hi/lo split, 3 passes: Ah.Bh + Al.Bh + Ah.Bl  (residual ~2^-22).

#define HH 224
#define WW 224
#define NB 32
#define NF 64
#define TPX 112
#define THREADS 256
#define NCTA 444                   // 3 * 148, persistent
#define NTILES (NB * HH * 2)       // 14336

// SMEM layout (bytes from dynamic base). A rows: 72 halves = 144B stride.
#define S_AH 0                     // 128 x 144 = 18432
#define S_AL 18432                 // 18432   (C f32 [64][132] overlays S_AH..)
#define S_BH 36864                 // 64 x 144 = 9216
#define S_BL 46080                 // 9216
#define S_RH 55296                 // raw hi: 7 rows x 120 halves = 1680
#define S_RL (S_RH + 1680)
#define S_TOT (S_RL + 1680)        // 58656

#define CSTRIDE 132                // C row stride in f32 (conflict-free)

__device__ __forceinline__ uint32_t smem_u32(const void* p) {
    uint32_t a;
    asm("{ .reg .u64 t; cvta.to.shared.u64 t, %1; cvt.u32.u64 %0, t; }" : "=r"(a) : "l"(p));
    return a;
}
__device__ __forceinline__ void sts16(uint32_t a, uint32_t v) {
    asm volatile("st.shared.u16 [%0], %1;" :: "r"(a), "r"(v) : "memory");
}
__device__ __forceinline__ uint32_t lds16(uint32_t a) {
    uint32_t v;
    asm volatile("ld.shared.u16 %0, [%1];" : "=r"(v) : "r"(a));
    return v;
}
__device__ __forceinline__ void sts32f(uint32_t a, float v) {
    asm volatile("st.shared.f32 [%0], %1;" :: "r"(a), "f"(v) : "memory");
}
__device__ __forceinline__ void sts128(uint32_t a, uint32_t r0, uint32_t r1,
                                       uint32_t r2, uint32_t r3) {
    asm volatile("st.shared.v4.b32 [%0], {%1, %2, %3, %4};"
                 :: "r"(a), "r"(r0), "r"(r1), "r"(r2), "r"(r3) : "memory");
}
__device__ __forceinline__ float4 lds128f(uint32_t a) {
    float4 v;
    asm volatile("ld.shared.v4.f32 {%0, %1, %2, %3}, [%4];"
                 : "=f"(v.x), "=f"(v.y), "=f"(v.z), "=f"(v.w) : "r"(a));
    return v;
}

#define LDSM4(r, addr) \
    asm volatile("ldmatrix.sync.aligned.m8n8.x4.shared.b16 {%0,%1,%2,%3}, [%4];" \
        : "=r"((r)[0]), "=r"((r)[1]), "=r"((r)[2]), "=r"((r)[3]) : "r"(addr))

#define MMA16816(c, a, bb0, bb1) \
    asm volatile("mma.sync.aligned.m16n8k16.row.col.f32.f16.f16.f32 " \
        "{%0,%1,%2,%3}, {%4,%5,%6,%7}, {%8,%9}, {%0,%1,%2,%3};" \
        : "+f"((c)[0]), "+f"((c)[1]), "+f"((c)[2]), "+f"((c)[3]) \
        : "r"((a)[0]), "r"((a)[1]), "r"((a)[2]), "r"((a)[3]), "r"(bb0), "r"(bb1))

__device__ __forceinline__ void split_h(float v, uint32_t& hi, uint32_t& lo) {
    __half h = __float2half(v);
    float r = v - __half2float(h);
    __half l = __float2half(r);
    hi = (uint32_t)__half_as_ushort(h);
    lo = (uint32_t)__half_as_ushort(l);
}

__global__ void __launch_bounds__(THREADS)
conv7x7_mma_kernel(const float* __restrict__ in,
                   const float* __restrict__ wk,
                   float* __restrict__ out) {
    extern __shared__ char smem[];
    const uint32_t sb = smem_u32(smem);
    const int tid = threadIdx.x;
    const int lane = tid & 31;
    const int wid = tid >> 5;

    // ---- one-time init: zero A (incl. k>=56 cols) + B regions ----
    for (int i = tid * 16; i < S_RH; i += THREADS * 16)
        sts128(sb + i, 0u, 0u, 0u, 0u);

    __syncthreads();

    // ---- weights -> B_hi/B_lo, [f][k=ky*8+kx], row stride 144B ----
    for (int i = tid; i < NF * 49; i += THREADS) {
        int f = i / 49, q = i - f * 49;
        int ky = q / 7, kx = q - ky * 7;
        uint32_t hi, lo;
        split_h(wk[i], hi, lo);
        uint32_t off = (uint32_t)(f * 144 + (ky * 8 + kx) * 2);
        sts16(sb + S_BH + off, hi);
        sts16(sb + S_BL + off, lo);
    }
    __syncthreads();

    // ---- per-warp ldmatrix lane offsets ----
    const int wm = wid & 3;          // m-tile of warp (4)
    const int wn = wid >> 2;         // n-tile of warp (2)
    // A x4: rows mbase + lane%16, k-half = lane/16
    const uint32_t aoff = (uint32_t)((wm * 32 + (lane & 15)) * 144 + (lane >> 4) * 16);
    // B x4: rows nbase + lane%8 + 8*(lane/16), k-half = (lane>>3)&1
    const uint32_t boff = (uint32_t)((wn * 32 + (lane & 7) + ((lane >> 4) & 1) * 8) * 144
                                     + ((lane >> 3) & 1) * 16);

    for (int tile = blockIdx.x; tile < NTILES; tile += NCTA) {
        const int b = tile / (HH * 2);
        const int r = tile - b * (HH * 2);
        const int y = r >> 1;
        const int x0 = (r & 1) * TPX;
        const float* inb = in + (size_t)b * (HH * WW);

        // ---- phase 1: stage raw rows (7 x 120 halves, hi+lo) ----
        for (int i = tid; i < 7 * 120; i += THREADS) {
            int rr = i / 120, c = i - rr * 120;
            int gy = y - 3 + rr, gx = x0 - 3 + c;
            float v = 0.0f;
            if (gy >= 0 && gy < HH && c < 118 && gx >= 0 && gx < WW)
                v = inb[gy * WW + gx];
            uint32_t hi, lo;
            split_h(v, hi, lo);
            sts16(sb + S_RH + i * 2, hi);
            sts16(sb + S_RL + i * 2, lo);
        }
        __syncthreads();

        // ---- phase 2: im2col A rows (cols 0..55) + re-zero cols 56..63 ----
        {
            const int sp = tid >> 7;        // 0 = hi, 1 = lo
            const int m = tid & 127;
            if (m < TPX) {
                const uint32_t rb = sb + (sp ? S_RL : S_RH) + (uint32_t)m * 2;
                const uint32_t ab = sb + (sp ? S_AL : S_AH) + (uint32_t)m * 144;
                #pragma unroll
                for (int ky = 0; ky < 7; ky++) {
                    uint32_t ra = rb + (uint32_t)(ky * 240);
                    uint32_t t0 = lds16(ra + 0),  t1 = lds16(ra + 2);
                    uint32_t t2 = lds16(ra + 4),  t3 = lds16(ra + 6);
                    uint32_t t4 = lds16(ra + 8),  t5 = lds16(ra + 10);
                    uint32_t t6 = lds16(ra + 12), t7 = lds16(ra + 14);
                    sts128(ab + ky * 16,
                           t0 | (t1 << 16), t2 | (t3 << 16),
                           t4 | (t5 << 16), t6 | (t7 << 16));
                }
                // kill stale C-f32 bits in cols 56..63 (read by mma, B=0 there,
                // but must be finite to avoid NaN*0)
                sts128(ab + 112, 0u, 0u, 0u, 0u);
            }
        }
        __syncthreads();

        // ---- phase 3: 3-pass warp MMA, acc[(im*4+in)*4 + c] ----
        float acc[32];
        #pragma unroll
        for (int i = 0; i < 32; i++) acc[i] = 0.0f;

        #pragma unroll
        for (int p = 0; p < 3; p++) {
            const uint32_t Ab = sb + (p == 1 ? S_AL : S_AH) + aoff;
            const uint32_t Bb = sb + (p == 2 ? S_BL : S_BH) + boff;
            #pragma unroll
            for (int k = 0; k < 4; k++) {
                uint32_t a0[4], a1[4], b0[4], b1[4];
                LDSM4(a0, Ab + k * 32);            // m-tile 0
                LDSM4(a1, Ab + 2304 + k * 32);     // m-tile 1 (+16 rows)
                LDSM4(b0, Bb + k * 32);            // n-tiles 0,1
                LDSM4(b1, Bb + 2304 + k * 32);     // n-tiles 2,3 (+16 rows)
                MMA16816(acc + 0,  a0, b0[0], b0[1]);
                MMA16816(acc + 4,  a0, b0[2], b0[3]);
                MMA16816(acc + 8,  a0, b1[0], b1[1]);
                MMA16816(acc + 12, a0, b1[2], b1[3]);
                MMA16816(acc + 16, a1, b0[0], b0[1]);
                MMA16816(acc + 20, a1, b0[2], b0[3]);
                MMA16816(acc + 24, a1, b1[0], b1[1]);
                MMA16816(acc + 28, a1, b1[2], b1[3]);
            }
        }
        __syncthreads();   // all warps done reading A before C overlay write

        // ---- phase 4: stage C[n][m] f32 (overlays A region) ----
        {
            const int tg = lane & 3, gp = lane >> 2;
            #pragma unroll
            for (int im = 0; im < 2; im++) {
                #pragma unroll
                for (int in_ = 0; in_ < 4; in_++) {
                    const float* a = &acc[(im * 4 + in_) * 4];
                    int n0 = wn * 32 + in_ * 8 + 2 * tg;
                    int m0 = wm * 32 + im * 16 + gp;
                    uint32_t c00 = sb + (uint32_t)((n0 * CSTRIDE + m0) * 4);
                    sts32f(c00, a[0]);                       // (n0,   m0)
                    sts32f(c00 + CSTRIDE * 4, a[1]);         // (n0+1, m0)
                    sts32f(c00 + 32, a[2]);                  // (n0,   m0+8)
                    sts32f(c00 + CSTRIDE * 4 + 32, a[3]);    // (n0+1, m0+8)
                }
            }
        }
        __syncthreads();

        // ---- phase 5: coalesced store, 4 threads per filter ----
        {
            const int f = tid >> 2, l4 = tid & 3;
            float* po = out + (size_t)b * (NF * HH * WW)
                            + (size_t)f * (HH * WW) + y * WW + x0;
            #pragma unroll
            for (int i = 0; i < 7; i++) {
                int m = i * 16 + l4 * 4;
                float4 v = lds128f(sb + (uint32_t)((f * CSTRIDE + m) * 4));
                *(float4*)(po + m) = v;
            }
        }
        __syncthreads();   // C reads done before next tile's im2col overwrite
    }
}

extern "C" void kernel_launch(void* const* d_in, const int* in_sizes, int n_in,
                              void* d_out, int out_size) {
    const float* x = (const float*)d_in[0];   // (32,1,224,224) f32
    const float* k = (const float*)d_in[1];   // (64,7,7) f32
    float* out = (float*)d_out;               // (32,64,224,224) f32

    cudaFuncSetAttribute(conv7x7_mma_kernel,
                         cudaFuncAttributeMaxDynamicSharedMemorySize, S_TOT);
    conv7x7_mma_kernel<<<NCTA, THREADS, S_TOT>>>(x, k, out);
}

// round 7
// speedup vs baseline: 1.6610x; 1.6610x over previous
#include <cuda_runtime.h>
#include <cuda_fp16.h>
#include <cstdint>

// Conv 7x7 C=1 as implicit GEMM via mma.sync (legacy HMMA; tcgen05 rejected by
// family-level compute_103 target). fp16 hi/lo split, 3 passes.
// Tile = 4 rows x 32 px (M=128, all valid) x 64 filters, K=64 (k=ky*8+kx).
// cp.async double-buffered raw input; split-once packed hi|lo staging.

#define HH 224
#define WW 224
#define NB 32
#define NF 64
#define THREADS 256
#define NCTA 296                    // 2 * 148, persistent
#define TY 4
#define TX 32
#define TPI 392                     // tiles per image: 56 * 7
#define NTILES (NB * TPI)           // 12544
#define RAWR 10
#define RAWC 38
#define RAWN (RAWR * RAWC)          // 380

// SMEM layout (bytes). A rows: 72 halves = 144B stride.
#define S_AH 0                      // 128 x 144 = 18432
#define S_AL 18432
#define S_BH 36864                  // 64 x 144 = 9216
#define S_BL 46080
#define S_RF 55296                  // raw f32, 2 buffers x 1520
#define S_RHL 58336                 // packed hi|lo u32, 381 elems = 1524
#define S_TOT 59872

#define CSTRIDE 132                 // C f32 overlay row stride (over A region)

__device__ __forceinline__ uint32_t smem_u32(const void* p) {
    uint32_t a;
    asm("{ .reg .u64 t; cvta.to.shared.u64 t, %1; cvt.u32.u64 %0, t; }" : "=r"(a) : "l"(p));
    return a;
}
__device__ __forceinline__ void sts16(uint32_t a, uint32_t v) {
    asm volatile("st.shared.u16 [%0], %1;" :: "r"(a), "r"(v) : "memory");
}
__device__ __forceinline__ void sts32(uint32_t a, uint32_t v) {
    asm volatile("st.shared.b32 [%0], %1;" :: "r"(a), "r"(v) : "memory");
}
__device__ __forceinline__ void sts32f(uint32_t a, float v) {
    asm volatile("st.shared.f32 [%0], %1;" :: "r"(a), "f"(v) : "memory");
}
__device__ __forceinline__ uint32_t lds32(uint32_t a) {
    uint32_t v;
    asm volatile("ld.shared.b32 %0, [%1];" : "=r"(v) : "r"(a));
    return v;
}
__device__ __forceinline__ float lds32f(uint32_t a) {
    float v;
    asm volatile("ld.shared.f32 %0, [%1];" : "=f"(v) : "r"(a));
    return v;
}
__device__ __forceinline__ void sts128(uint32_t a, uint32_t r0, uint32_t r1,
                                       uint32_t r2, uint32_t r3) {
    asm volatile("st.shared.v4.b32 [%0], {%1, %2, %3, %4};"
                 :: "r"(a), "r"(r0), "r"(r1), "r"(r2), "r"(r3) : "memory");
}
__device__ __forceinline__ float4 lds128f(uint32_t a) {
    float4 v;
    asm volatile("ld.shared.v4.f32 {%0, %1, %2, %3}, [%4];"
                 : "=f"(v.x), "=f"(v.y), "=f"(v.z), "=f"(v.w) : "r"(a));
    return v;
}
__device__ __forceinline__ void cpasync4(uint32_t dst, const void* src, uint32_t sz) {
    asm volatile("cp.async.ca.shared.global [%0], [%1], 4, %2;"
                 :: "r"(dst), "l"(src), "r"(sz) : "memory");
}
#define CP_COMMIT() asm volatile("cp.async.commit_group;" ::: "memory")
#define CP_WAIT0()  asm volatile("cp.async.wait_group 0;" ::: "memory")

#define LDSM4(r, addr) \
    asm volatile("ldmatrix.sync.aligned.m8n8.x4.shared.b16 {%0,%1,%2,%3}, [%4];" \
        : "=r"((r)[0]), "=r"((r)[1]), "=r"((r)[2]), "=r"((r)[3]) : "r"(addr))

#define MMA16816(c, a, bb0, bb1) \
    asm volatile("mma.sync.aligned.m16n8k16.row.col.f32.f16.f16.f32 " \
        "{%0,%1,%2,%3}, {%4,%5,%6,%7}, {%8,%9}, {%0,%1,%2,%3};" \
        : "+f"((c)[0]), "+f"((c)[1]), "+f"((c)[2]), "+f"((c)[3]) \
        : "r"((a)[0]), "r"((a)[1]), "r"((a)[2]), "r"((a)[3]), "r"(bb0), "r"(bb1))

__device__ __forceinline__ void split_h(float v, uint32_t& hi, uint32_t& lo) {
    __half h = __float2half(v);
    float r = v - __half2float(h);
    __half l = __float2half(r);
    hi = (uint32_t)__half_as_ushort(h);
    lo = (uint32_t)__half_as_ushort(l);
}

__global__ void __launch_bounds__(THREADS)
conv7x7_mma2_kernel(const float* __restrict__ in,
                    const float* __restrict__ wk,
                    float* __restrict__ out) {
    extern __shared__ char smem[];
    const uint32_t sb = smem_u32(smem);
    const int tid = threadIdx.x;
    const int lane = tid & 31;
    const int wid = tid >> 5;

    // ---- one-time init: zero B region + rawhl overread pad ----
    for (int i = S_BH + tid * 16; i < S_RF; i += THREADS * 16)
        sts128(sb + i, 0u, 0u, 0u, 0u);
    if (tid == 0) sts32(sb + S_RHL + RAWN * 4, 0u);   // finite pad for kx=7 corner
    __syncthreads();

    // ---- weights -> B_hi/B_lo, [f][k=ky*8+kx], row stride 144B ----
    for (int i = tid; i < NF * 49; i += THREADS) {
        int f = i / 49, q = i - f * 49;
        int ky = q / 7, kx = q - ky * 7;
        uint32_t hi, lo;
        split_h(wk[i], hi, lo);
        uint32_t off = (uint32_t)(f * 144 + (ky * 8 + kx) * 2);
        sts16(sb + S_BH + off, hi);
        sts16(sb + S_BL + off, lo);
    }

    // ---- per-warp ldmatrix lane offsets ----
    const int wm = wid & 3;          // m-tile (4)
    const int wn = wid >> 2;         // n-tile (2)
    const uint32_t aoff = (uint32_t)((wm * 32 + (lane & 15)) * 144 + (lane >> 4) * 16);
    const uint32_t boff = (uint32_t)((wn * 32 + (lane & 7) + ((lane >> 4) & 1) * 8) * 144
                                     + ((lane >> 3) & 1) * 16);

    // ---- raw issue helper (cp.async f32 rows, zfill OOB) ----
    auto issue_raw = [&](int tile, int buf) {
        const int b = tile / TPI;
        const int rem = tile - b * TPI;
        const int yp = rem / 7;
        const int xh = rem - yp * 7;
        const int y0 = yp * TY, x0 = xh * TX;
        const float* inb = in + (size_t)b * (HH * WW);
        #pragma unroll
        for (int it = 0; it < 2; it++) {
            int i = tid + it * THREADS;
            if (i < RAWN) {
                int r = i / RAWC, c = i - r * RAWC;
                int gy = y0 - 3 + r, gx = x0 - 3 + c;
                bool ok = (gy >= 0 && gy < HH && gx >= 0 && gx < WW);
                const float* src = ok ? (inb + gy * WW + gx) : inb;
                cpasync4(sb + S_RF + buf * 1520 + (uint32_t)i * 4, src, ok ? 4u : 0u);
            }
        }
    };

    int buf = 0;
    if (blockIdx.x < NTILES) issue_raw(blockIdx.x, 0);
    CP_COMMIT();

    for (int tile = blockIdx.x; tile < NTILES; tile += NCTA) {
        const int b = tile / TPI;
        const int rem = tile - b * TPI;
        const int yp = rem / 7;
        const int xh = rem - yp * 7;
        const int y0 = yp * TY, x0 = xh * TX;

        CP_WAIT0();
        __syncthreads();   // raw[buf] visible; prev tile phase5 reads done

        // ---- phase 1: split raw f32 -> packed (hi | lo<<16) ----
        #pragma unroll
        for (int it = 0; it < 2; it++) {
            int i = tid + it * THREADS;
            if (i < RAWN) {
                float v = lds32f(sb + S_RF + buf * 1520 + (uint32_t)i * 4);
                uint32_t hi, lo;
                split_h(v, hi, lo);
                sts32(sb + S_RHL + (uint32_t)i * 4, hi | (lo << 16));
            }
        }

        // prefetch next tile's raw
        {
            int nt = tile + NCTA;
            if (nt < NTILES) issue_raw(nt, buf ^ 1);
            CP_COMMIT();
        }
        __syncthreads();   // rawhl ready

        // ---- phase 2: im2col -> A_hi + A_lo (from same loads), zero cols 56-63 ----
        {
            const int m = tid & 127;          // m = dy*32 + x
            const int half = tid >> 7;
            const int dy = m >> 5, x = m & 31;
            const int ky0 = half ? 4 : 0, ky1 = half ? 7 : 4;
            const uint32_t ah = sb + S_AH + (uint32_t)m * 144;
            const uint32_t al = sb + S_AL + (uint32_t)m * 144;
            for (int ky = ky0; ky < ky1; ky++) {
                uint32_t ra = sb + S_RHL + (uint32_t)(((dy + ky) * RAWC + x) * 4);
                uint32_t w0 = lds32(ra + 0),  w1 = lds32(ra + 4);
                uint32_t w2 = lds32(ra + 8),  w3 = lds32(ra + 12);
                uint32_t w4 = lds32(ra + 16), w5 = lds32(ra + 20);
                uint32_t w6 = lds32(ra + 24), w7 = lds32(ra + 28);
                sts128(ah + ky * 16,
                       __byte_perm(w0, w1, 0x5410), __byte_perm(w2, w3, 0x5410),
                       __byte_perm(w4, w5, 0x5410), __byte_perm(w6, w7, 0x5410));
                sts128(al + ky * 16,
                       __byte_perm(w0, w1, 0x7632), __byte_perm(w2, w3, 0x7632),
                       __byte_perm(w4, w5, 0x7632), __byte_perm(w6, w7, 0x7632));
            }
            // re-zero k 56..63 (C overlay leaves stale f32 bits; B=0 there but must be finite)
            sts128((half ? al : ah) + 112, 0u, 0u, 0u, 0u);
        }
        __syncthreads();   // A ready

        // ---- phase 3: 3-pass warp MMA ----
        float acc[32];
        #pragma unroll
        for (int i = 0; i < 32; i++) acc[i] = 0.0f;

        #pragma unroll
        for (int p = 0; p < 3; p++) {
            const uint32_t Ab = sb + (p == 1 ? S_AL : S_AH) + aoff;
            const uint32_t Bb = sb + (p == 2 ? S_BL : S_BH) + boff;
            #pragma unroll
            for (int k = 0; k < 4; k++) {
                uint32_t a0[4], a1[4], b0[4], b1[4];
                LDSM4(a0, Ab + k * 32);
                LDSM4(a1, Ab + 2304 + k * 32);
                LDSM4(b0, Bb + k * 32);
                LDSM4(b1, Bb + 2304 + k * 32);
                MMA16816(acc + 0,  a0, b0[0], b0[1]);
                MMA16816(acc + 4,  a0, b0[2], b0[3]);
                MMA16816(acc + 8,  a0, b1[0], b1[1]);
                MMA16816(acc + 12, a0, b1[2], b1[3]);
                MMA16816(acc + 16, a1, b0[0], b0[1]);
                MMA16816(acc + 20, a1, b0[2], b0[3]);
                MMA16816(acc + 24, a1, b1[0], b1[1]);
                MMA16816(acc + 28, a1, b1[2], b1[3]);
            }
        }
        __syncthreads();   // A reads done before C overlay

        // ---- phase 4: stage C[n][m] f32 over A region ----
        {
            const int tg = lane & 3, gp = lane >> 2;
            #pragma unroll
            for (int im = 0; im < 2; im++) {
                #pragma unroll
                for (int in_ = 0; in_ < 4; in_++) {
                    const float* a = &acc[(im * 4 + in_) * 4];
                    int n0 = wn * 32 + in_ * 8 + 2 * tg;
                    int m0 = wm * 32 + im * 16 + gp;
                    uint32_t c00 = sb + (uint32_t)((n0 * CSTRIDE + m0) * 4);
                    sts32f(c00, a[0]);
                    sts32f(c00 + CSTRIDE * 4, a[1]);
                    sts32f(c00 + 32, a[2]);
                    sts32f(c00 + CSTRIDE * 4 + 32, a[3]);
                }
            }
        }
        __syncthreads();   // C ready

        // ---- phase 5: coalesced 128B stores, 8 lanes per (f,dy) row ----
        {
            const int p0 = tid >> 3, j = tid & 7;
            #pragma unroll
            for (int it = 0; it < 8; it++) {
                int p = p0 + it * 32;        // (f, dy) pair
                int f = p >> 2, dy = p & 3;
                int m = dy * 32 + j * 4;
                float4 v = lds128f(sb + (uint32_t)((f * CSTRIDE + m) * 4));
                float* po = out + (size_t)b * (NF * HH * WW)
                                + (size_t)f * (HH * WW) + (y0 + dy) * WW + x0;
                *(float4*)(po + j * 4) = v;
            }
        }
        buf ^= 1;
        // loop-top __syncthreads orders phase-5 C reads before next im2col write
    }
}

extern "C" void kernel_launch(void* const* d_in, const int* in_sizes, int n_in,
                              void* d_out, int out_size) {
    const float* x = (const float*)d_in[0];   // (32,1,224,224) f32
    const float* k = (const float*)d_in[1];   // (64,7,7) f32
    float* out = (float*)d_out;               // (32,64,224,224) f32

    cudaFuncSetAttribute(conv7x7_mma2_kernel,
                         cudaFuncAttributeMaxDynamicSharedMemorySize, S_TOT);
    conv7x7_mma2_kernel<<<NCTA, THREADS, S_TOT>>>(x, k, out);
}

// round 8
// speedup vs baseline: 2.1850x; 1.3155x over previous
#include <cuda_runtime.h>
#include <cuda_fp16.h>
#include <cstdint>

// Conv 7x7 C=1 implicit GEMM via mma.sync (legacy HMMA; tcgen05 rejected by
// family-level compute_103 target). 2-pass fp16: Ah.B + Al.B, B = RN fp16
// (weight-quantization error ~1e-4 norm-relative, 10x under 1e-3 gate).
// Tile = 4 rows x 32 px (M=128) x 64 filters, K=64 (k=ky*8+kx).
// B fragments register-resident (loaded once); cp.async double-buffered input;
// split-once packed hi|lo staging; separate C buffer (no A overlay).

#define HH 224
#define WW 224
#define NB 32
#define NF 64
#define THREADS 256
#define NCTA 296                    // 2 * 148, persistent
#define TY 4
#define TX 32
#define TPI 392                     // 56 * 7 tiles per image
#define NTILES (NB * TPI)           // 12544
#define RAWR 10
#define RAWC 38
#define RAWN (RAWR * RAWC)          // 380

// SMEM layout (bytes). A rows: 72 halves = 144B stride.
#define S_AH 0                      // 128 x 144 = 18432
#define S_AL 18432                  // -> 36864
#define S_B  36864                  // 64 x 144 = 9216 -> 46080
#define S_C  46080                  // 64 x 132 x 4 = 33792 -> 79872
#define S_RF 79872                  // raw f32, 2 x 1520 -> 82912
#define S_RHL 82912                 // packed hi|lo u32, 381 -> 84436
#define S_TOT 84448

#define CSTRIDE 132                 // C row stride in f32

__device__ __forceinline__ uint32_t smem_u32(const void* p) {
    uint32_t a;
    asm("{ .reg .u64 t; cvta.to.shared.u64 t, %1; cvt.u32.u64 %0, t; }" : "=r"(a) : "l"(p));
    return a;
}
__device__ __forceinline__ void sts16(uint32_t a, uint32_t v) {
    asm volatile("st.shared.u16 [%0], %1;" :: "r"(a), "r"(v) : "memory");
}
__device__ __forceinline__ void sts32(uint32_t a, uint32_t v) {
    asm volatile("st.shared.b32 [%0], %1;" :: "r"(a), "r"(v) : "memory");
}
__device__ __forceinline__ void sts32f(uint32_t a, float v) {
    asm volatile("st.shared.f32 [%0], %1;" :: "r"(a), "f"(v) : "memory");
}
__device__ __forceinline__ uint32_t lds32(uint32_t a) {
    uint32_t v;
    asm volatile("ld.shared.b32 %0, [%1];" : "=r"(v) : "r"(a));
    return v;
}
__device__ __forceinline__ float lds32f(uint32_t a) {
    float v;
    asm volatile("ld.shared.f32 %0, [%1];" : "=f"(v) : "r"(a));
    return v;
}
__device__ __forceinline__ void sts128(uint32_t a, uint32_t r0, uint32_t r1,
                                       uint32_t r2, uint32_t r3) {
    asm volatile("st.shared.v4.b32 [%0], {%1, %2, %3, %4};"
                 :: "r"(a), "r"(r0), "r"(r1), "r"(r2), "r"(r3) : "memory");
}
__device__ __forceinline__ float4 lds128f(uint32_t a) {
    float4 v;
    asm volatile("ld.shared.v4.f32 {%0, %1, %2, %3}, [%4];"
                 : "=f"(v.x), "=f"(v.y), "=f"(v.z), "=f"(v.w) : "r"(a));
    return v;
}
__device__ __forceinline__ void cpasync4(uint32_t dst, const void* src, uint32_t sz) {
    asm volatile("cp.async.ca.shared.global [%0], [%1], 4, %2;"
                 :: "r"(dst), "l"(src), "r"(sz) : "memory");
}
#define CP_COMMIT() asm volatile("cp.async.commit_group;" ::: "memory")
#define CP_WAIT0()  asm volatile("cp.async.wait_group 0;" ::: "memory")

#define LDSM4(r, addr) \
    asm volatile("ldmatrix.sync.aligned.m8n8.x4.shared.b16 {%0,%1,%2,%3}, [%4];" \
        : "=r"((r)[0]), "=r"((r)[1]), "=r"((r)[2]), "=r"((r)[3]) : "r"(addr))

#define MMA16816(c, a, bb0, bb1) \
    asm volatile("mma.sync.aligned.m16n8k16.row.col.f32.f16.f16.f32 " \
        "{%0,%1,%2,%3}, {%4,%5,%6,%7}, {%8,%9}, {%0,%1,%2,%3};" \
        : "+f"((c)[0]), "+f"((c)[1]), "+f"((c)[2]), "+f"((c)[3]) \
        : "r"((a)[0]), "r"((a)[1]), "r"((a)[2]), "r"((a)[3]), "r"(bb0), "r"(bb1))

__device__ __forceinline__ void split_h(float v, uint32_t& hi, uint32_t& lo) {
    __half h = __float2half(v);
    float r = v - __half2float(h);
    __half l = __float2half(r);
    hi = (uint32_t)__half_as_ushort(h);
    lo = (uint32_t)__half_as_ushort(l);
}

__global__ void __launch_bounds__(THREADS, 2)
conv7x7_mma3_kernel(const float* __restrict__ in,
                    const float* __restrict__ wk,
                    float* __restrict__ out) {
    extern __shared__ char smem[];
    const uint32_t sb = smem_u32(smem);
    const int tid = threadIdx.x;
    const int lane = tid & 31;
    const int wid = tid >> 5;

    // ---- one-time init: zero A_hi, A_lo, B regions + rawhl overread pad ----
    for (int i = tid * 16; i < S_C; i += THREADS * 16)
        sts128(sb + i, 0u, 0u, 0u, 0u);
    if (tid == 0) sts32(sb + S_RHL + RAWN * 4, 0u);   // finite pad, kx=7 corner
    __syncthreads();

    // ---- weights -> B fp16 (RN), [f][k=ky*8+kx], row stride 144B ----
    for (int i = tid; i < NF * 49; i += THREADS) {
        int f = i / 49, q = i - f * 49;
        int ky = q / 7, kx = q - ky * 7;
        uint32_t h = (uint32_t)__half_as_ushort(__float2half(wk[i]));
        sts16(sb + S_B + (uint32_t)(f * 144 + (ky * 8 + kx) * 2), h);
    }
    __syncthreads();

    // ---- per-warp ldmatrix lane offsets ----
    const int wm = wid & 3;          // m-tile (4)
    const int wn = wid >> 2;         // n-tile (2)
    const uint32_t aoff = (uint32_t)((wm * 32 + (lane & 15)) * 144 + (lane >> 4) * 16);
    const uint32_t boff = (uint32_t)((wn * 32 + (lane & 7) + ((lane >> 4) & 1) * 8) * 144
                                     + ((lane >> 3) & 1) * 16);

    // ---- B fragments: register-resident for the whole kernel ----
    uint32_t bf[4][8];
    #pragma unroll
    for (int k = 0; k < 4; k++) {
        LDSM4(&bf[k][0], sb + S_B + boff + k * 32);          // n-tiles 0,1
        LDSM4(&bf[k][4], sb + S_B + boff + 2304 + k * 32);   // n-tiles 2,3
    }

    // ---- raw issue helper (cp.async f32, zfill OOB) ----
    auto issue_raw = [&](int tile, int buf) {
        const int b = tile / TPI;
        const int rem = tile - b * TPI;
        const int yp = rem / 7;
        const int xh = rem - yp * 7;
        const int y0 = yp * TY, x0 = xh * TX;
        const float* inb = in + (size_t)b * (HH * WW);
        #pragma unroll
        for (int it = 0; it < 2; it++) {
            int i = tid + it * THREADS;
            if (i < RAWN) {
                int r = i / RAWC, c = i - r * RAWC;
                int gy = y0 - 3 + r, gx = x0 - 3 + c;
                bool ok = (gy >= 0 && gy < HH && gx >= 0 && gx < WW);
                const float* src = ok ? (inb + gy * WW + gx) : inb;
                cpasync4(sb + S_RF + buf * 1520 + (uint32_t)i * 4, src, ok ? 4u : 0u);
            }
        }
    };

    int buf = 0;
    if (blockIdx.x < NTILES) issue_raw(blockIdx.x, 0);
    CP_COMMIT();

    for (int tile = blockIdx.x; tile < NTILES; tile += NCTA) {
        const int b = tile / TPI;
        const int rem = tile - b * TPI;
        const int yp = rem / 7;
        const int xh = rem - yp * 7;
        const int y0 = yp * TY, x0 = xh * TX;

        CP_WAIT0();
        __syncthreads();   // raw[buf] visible; prev tile done with A/C

        // ---- phase 1: split raw f32 -> packed (hi | lo<<16) ----
        #pragma unroll
        for (int it = 0; it < 2; it++) {
            int i = tid + it * THREADS;
            if (i < RAWN) {
                float v = lds32f(sb + S_RF + buf * 1520 + (uint32_t)i * 4);
                uint32_t hi, lo;
                split_h(v, hi, lo);
                sts32(sb + S_RHL + (uint32_t)i * 4, hi | (lo << 16));
            }
        }

        // prefetch next tile's raw into other buffer
        {
            int nt = tile + NCTA;
            if (nt < NTILES) issue_raw(nt, buf ^ 1);
            CP_COMMIT();
        }
        __syncthreads();   // rawhl ready

        // ---- phase 2: im2col -> A_hi + A_lo from same loads ----
        {
            const int m = tid & 127;          // m = dy*32 + x
            const int half = tid >> 7;
            const int dy = m >> 5, x = m & 31;
            const int ky0 = half ? 4 : 0, ky1 = half ? 7 : 4;
            const uint32_t ah = sb + S_AH + (uint32_t)m * 144;
            const uint32_t al = sb + S_AL + (uint32_t)m * 144;
            for (int ky = ky0; ky < ky1; ky++) {
                uint32_t ra = sb + S_RHL + (uint32_t)(((dy + ky) * RAWC + x) * 4);
                uint32_t w0 = lds32(ra + 0),  w1 = lds32(ra + 4);
                uint32_t w2 = lds32(ra + 8),  w3 = lds32(ra + 12);
                uint32_t w4 = lds32(ra + 16), w5 = lds32(ra + 20);
                uint32_t w6 = lds32(ra + 24), w7 = lds32(ra + 28);
                sts128(ah + ky * 16,
                       __byte_perm(w0, w1, 0x5410), __byte_perm(w2, w3, 0x5410),
                       __byte_perm(w4, w5, 0x5410), __byte_perm(w6, w7, 0x5410));
                sts128(al + ky * 16,
                       __byte_perm(w0, w1, 0x7632), __byte_perm(w2, w3, 0x7632),
                       __byte_perm(w4, w5, 0x7632), __byte_perm(w6, w7, 0x7632));
            }
        }
        __syncthreads();   // A ready

        // ---- phase 3: 2-pass warp MMA (B frags resident) ----
        float acc[32];
        #pragma unroll
        for (int i = 0; i < 32; i++) acc[i] = 0.0f;

        #pragma unroll
        for (int p = 0; p < 2; p++) {
            const uint32_t Ab = sb + (p ? S_AL : S_AH) + aoff;
            #pragma unroll
            for (int k = 0; k < 4; k++) {
                uint32_t a0[4], a1[4];
                LDSM4(a0, Ab + k * 32);            // m-tile 0
                LDSM4(a1, Ab + 2304 + k * 32);     // m-tile 1
                MMA16816(acc + 0,  a0, bf[k][0], bf[k][1]);
                MMA16816(acc + 4,  a0, bf[k][2], bf[k][3]);
                MMA16816(acc + 8,  a0, bf[k][4], bf[k][5]);
                MMA16816(acc + 12, a0, bf[k][6], bf[k][7]);
                MMA16816(acc + 16, a1, bf[k][0], bf[k][1]);
                MMA16816(acc + 20, a1, bf[k][2], bf[k][3]);
                MMA16816(acc + 24, a1, bf[k][4], bf[k][5]);
                MMA16816(acc + 28, a1, bf[k][6], bf[k][7]);
            }
        }

        // ---- phase 4: stage C[n][m] f32 (separate buffer, no A hazard) ----
        {
            const int tg = lane & 3, gp = lane >> 2;
            #pragma unroll
            for (int im = 0; im < 2; im++) {
                #pragma unroll
                for (int in_ = 0; in_ < 4; in_++) {
                    const float* a = &acc[(im * 4 + in_) * 4];
                    int n0 = wn * 32 + in_ * 8 + 2 * tg;
                    int m0 = wm * 32 + im * 16 + gp;
                    uint32_t c00 = sb + S_C + (uint32_t)((n0 * CSTRIDE + m0) * 4);
                    sts32f(c00, a[0]);
                    sts32f(c00 + CSTRIDE * 4, a[1]);
                    sts32f(c00 + 32, a[2]);
                    sts32f(c00 + CSTRIDE * 4 + 32, a[3]);
                }
            }
        }
        __syncthreads();   // C ready

        // ---- phase 5: coalesced 128B stores, 8 lanes per (f,dy) row ----
        {
            const int p0 = tid >> 3, j = tid & 7;
            #pragma unroll
            for (int it = 0; it < 8; it++) {
                int p = p0 + it * 32;        // (f, dy) pair
                int f = p >> 2, dy = p & 3;
                int m = dy * 32 + j * 4;
                float4 v = lds128f(sb + S_C + (uint32_t)((f * CSTRIDE + m) * 4));
                float* po = out + (size_t)b * (NF * HH * WW)
                                + (size_t)f * (HH * WW) + (y0 + dy) * WW + x0;
                *(float4*)(po + j * 4) = v;
            }
        }
        buf ^= 1;
        // loop-top sync orders phase-5 C reads / MMA A reads before next writes
    }
}

extern "C" void kernel_launch(void* const* d_in, const int* in_sizes, int n_in,
                              void* d_out, int out_size) {
    const float* x = (const float*)d_in[0];   // (32,1,224,224) f32
    const float* k = (const float*)d_in[1];   // (64,7,7) f32
    float* out = (float*)d_out;               // (32,64,224,224) f32

    cudaFuncSetAttribute(conv7x7_mma3_kernel,
                         cudaFuncAttributeMaxDynamicSharedMemorySize, S_TOT);
    conv7x7_mma3_kernel<<<NCTA, THREADS, S_TOT>>>(x, k, out);
}